// round 4
// baseline (speedup 1.0000x reference)
#include <cuda_runtime.h>
#include <cstring>

#define S_LEN 512
#define BATCH 64
#define IDIM  256
#define HID   512
#define GH    1536   // 3*HID
#define ODIM  512    // 2*O

#define RSTR 68      // sred row stride in floats: 272B = 16B-aligned, conflict-free

// ---------------- scratch (static device globals; no allocation) -------------
__device__ float    g_gi[(size_t)BATCH * S_LEN * GH];          // [B*S][3H] (row = b*512+s)
__device__ float    g_hs[(size_t)S_LEN * BATCH * HID];         // [S][B][H] -> GEMM2
__device__ float    g_hsT[(size_t)(S_LEN + 1) * 4 * HID * 16]; // [step][grp][k][b16]
__device__ unsigned g_blk[4 * 8 * 64];                          // per-(grp,block) counters, 256B apart

// ---------------- packed f32x2 FMA (full-rate fp32 on sm_100a) ---------------
__device__ __forceinline__ float2 ffma2(float2 a, float2 b, float2 c) {
#if defined(__CUDA_ARCH__) && (__CUDA_ARCH__ >= 1000)
    unsigned long long au, bu, cu, du;
    memcpy(&au, &a, 8); memcpy(&bu, &b, 8); memcpy(&cu, &c, 8);
    asm("fma.rn.f32x2 %0, %1, %2, %3;" : "=l"(du) : "l"(au), "l"(bu), "l"(cu));
    float2 d; memcpy(&d, &du, 8);
    return d;
#else
    return make_float2(fmaf(a.x, b.x, c.x), fmaf(a.y, b.y, c.y));
#endif
}

__device__ __forceinline__ void poll_ge(const unsigned* a, unsigned need) {
    unsigned v;
    do {
        asm volatile("ld.acquire.gpu.global.u32 %0, [%1];" : "=r"(v) : "l"(a) : "memory");
    } while (v < need);
}

// =============================================================================
// Tiled GEMM: C[M][N] = A[M][K] * B[N][K]^T + bias[N]
// 128x128 CTA tile, BLK_K=16, 256 threads, 8x8 per-thread tile (4+4 split),
// f32x2 FMAs, 2 CTAs/SM.
// =============================================================================
template<int KDIM, int MODE>
__global__ __launch_bounds__(256, 2)
void gemm_tn(const float* __restrict__ A, const float* __restrict__ B,
             const float* __restrict__ bias, float* __restrict__ C)
{
    __shared__ float As[16 * 132];
    __shared__ float Bs[16 * 132];

    const int tid = threadIdx.x;
    const int m0 = blockIdx.y * 128;
    const int n0 = blockIdx.x * 128;
    const int lr = tid >> 2;
    const int lc = tid & 3;
    const int tx = tid & 15;
    const int ty = tid >> 4;

    const float* Ap = A + (size_t)(m0 + lr) * KDIM + lc * 4;
    const float* Bp = B + (size_t)(n0 + lr) * KDIM + lc * 4;

    float2 c2[8][4];
#pragma unroll
    for (int i = 0; i < 8; i++)
#pragma unroll
        for (int j = 0; j < 4; j++) c2[i][j] = make_float2(0.f, 0.f);

    float4 pa0 = *(const float4*)(Ap);
    float4 pa1 = *(const float4*)(Ap + (size_t)64 * KDIM);
    float4 pb0 = *(const float4*)(Bp);
    float4 pb1 = *(const float4*)(Bp + (size_t)64 * KDIM);

    const int KT = KDIM / 16;
    for (int kt = 0; kt < KT; kt++) {
        {
            const float* a0 = (const float*)&pa0;
            const float* a1 = (const float*)&pa1;
            const float* b0 = (const float*)&pb0;
            const float* b1 = (const float*)&pb1;
#pragma unroll
            for (int j = 0; j < 4; j++) {
                As[(lc * 4 + j) * 132 + lr]      = a0[j];
                As[(lc * 4 + j) * 132 + lr + 64] = a1[j];
                Bs[(lc * 4 + j) * 132 + lr]      = b0[j];
                Bs[(lc * 4 + j) * 132 + lr + 64] = b1[j];
            }
        }
        __syncthreads();
        if (kt + 1 < KT) {
            Ap += 16; Bp += 16;
            pa0 = *(const float4*)(Ap);
            pa1 = *(const float4*)(Ap + (size_t)64 * KDIM);
            pb0 = *(const float4*)(Bp);
            pb1 = *(const float4*)(Bp + (size_t)64 * KDIM);
        }
#pragma unroll
        for (int k = 0; k < 16; k++) {
            float4 a0 = *(const float4*)&As[k * 132 + ty * 4];
            float4 a1 = *(const float4*)&As[k * 132 + 64 + ty * 4];
            float4 b0 = *(const float4*)&Bs[k * 132 + tx * 4];
            float4 b1 = *(const float4*)&Bs[k * 132 + 64 + tx * 4];
            float av[8] = {a0.x, a0.y, a0.z, a0.w, a1.x, a1.y, a1.z, a1.w};
            float2 bv[4] = {{b0.x, b0.y}, {b0.z, b0.w}, {b1.x, b1.y}, {b1.z, b1.w}};
#pragma unroll
            for (int i = 0; i < 8; i++) {
                float2 ad = make_float2(av[i], av[i]);
#pragma unroll
                for (int j = 0; j < 4; j++) c2[i][j] = ffma2(ad, bv[j], c2[i][j]);
            }
        }
        __syncthreads();
    }

    int ncol[4];
    float2 bb[4];
#pragma unroll
    for (int j = 0; j < 4; j++) {
        ncol[j] = n0 + ((j < 2) ? (tx * 4 + 2 * j) : (64 + tx * 4 + 2 * (j - 2)));
        bb[j] = make_float2(bias[ncol[j]], bias[ncol[j] + 1]);
    }

#pragma unroll
    for (int i = 0; i < 8; i++) {
        int r = m0 + ((i < 4) ? (ty * 4 + i) : (64 + ty * 4 + (i - 4)));
        size_t rbase;
        if (MODE == 0) {
            rbase = (size_t)r * GH;
        } else {
            int s = r >> 6, b = r & 63;
            rbase = ((size_t)(b * S_LEN + s)) * ODIM;
        }
#pragma unroll
        for (int j = 0; j < 4; j++) {
            float2 v = make_float2(c2[i][j].x + bb[j].x, c2[i][j].y + bb[j].y);
            *(float2*)&C[rbase + ncol[j]] = v;
        }
    }
}

// =============================================================================
// GRU scan: 4 groups x 32 CTAs; slice = 16 j, weights register-resident.
// 288 threads: tid<256 = 16 kI x 16 jI compute; warp 8 = flag poller.
// Dataflow exchange: h split into 8 blocks of 64 k; per-(grp,blk) monotonic
// counters (4 producers each). Block loop overlaps [poll(i+1) || LDG(i+1)]
// with FMA(i). Weights loaded in processing order (cyclic from own block)
// so all register indices are compile-time.
// =============================================================================
__global__ __launch_bounds__(288, 1)
void gru_scan(const float* __restrict__ w_hh, const float* __restrict__ b_hh)
{
    extern __shared__ float sm[];
    float* sh_h = sm;                 // 512*16 floats: h_s [k][b16]
    float* sred = sm + 512 * 16;      // 256 rows x RSTR floats (16B-aligned rows)

    const int tid     = threadIdx.x;
    const int grp     = blockIdx.x >> 5;
    const int slice   = blockIdx.x & 31;
    const int j0      = slice * 16;
    const int b0      = grp * 16;
    const int own_blk = slice >> 2;
    const int kI      = (tid < 256) ? (tid >> 4) : 0;   // k interleave 0..15
    const int jI      = tid & 15;                       // hidden unit in slice
    const int jj      = kI;                             // gate-stage hidden idx
    const int bbat    = jI;                             // gate-stage batch idx

    // ---- register-resident weights, permuted into processing order ---------
    float w[3][32];
    if (tid < 256) {
#pragma unroll
        for (int g = 0; g < 3; g++) {
            const float* p = w_hh + (size_t)(g * HID + j0 + jI) * HID;
#pragma unroll
            for (int i = 0; i < 8; i++) {
                int blk = (own_blk + i) & 7;
#pragma unroll
                for (int mm = 0; mm < 4; mm++)
                    w[g][4 * i + mm] = p[kI + 16 * (4 * blk + mm)];
            }
        }
    }
    const float bh_r = b_hh[j0 + jj];
    const float bh_z = b_hh[HID + j0 + jj];
    const float bh_n = b_hh[2 * HID + j0 + jj];

    for (int i = tid; i < 512 * 16; i += 288) sh_h[i] = 0.f;   // h_0 = 0
    __syncthreads();

    for (int s = 0; s < S_LEN; s++) {
        // gi prefetch (consumed at gate stage)
        float gir = 0.f, giz = 0.f, gin = 0.f;
        if (tid < 256) {
            const float* gip = g_gi + ((size_t)((b0 + bbat) * S_LEN + s)) * GH + j0 + jj;
            gir = gip[0]; giz = gip[HID]; gin = gip[2 * HID];
        }

        float2 acc[8][3];
#pragma unroll
        for (int p = 0; p < 8; p++)
#pragma unroll
            for (int g = 0; g < 3; g++) acc[p][g] = make_float2(0.f, 0.f);

        if (s > 0) {
            const float* hsrc = g_hsT + ((size_t)s * 4 + grp) * (HID * 16);
            const unsigned need = 4u * (unsigned)s;

            if (tid == 256) poll_ge(&g_blk[(grp * 8 + own_blk) * 64], need);
            __syncthreads();

            float4 ld0 = make_float4(0.f, 0.f, 0.f, 0.f);
            if (tid < 256)
                ld0 = *(const float4*)(hsrc + (size_t)own_blk * 1024 + tid * 4);

#pragma unroll
            for (int i = 0; i < 8; i++) {
                const int blk = (own_blk + i) & 7;
                if (i < 7 && tid == 256)
                    poll_ge(&g_blk[(grp * 8 + ((own_blk + i + 1) & 7)) * 64], need);
                if (tid < 256)
                    *(float4*)(sh_h + blk * 1024 + tid * 4) = ld0;
                __syncthreads();
                if (i < 7 && tid < 256)
                    ld0 = *(const float4*)(hsrc + (size_t)((own_blk + i + 1) & 7) * 1024 + tid * 4);
                if (tid < 256) {
#pragma unroll
                    for (int mm = 0; mm < 4; mm++) {
                        const float* hr = sh_h + (kI + 16 * (4 * blk + mm)) * 16;
                        float2 wr = make_float2(w[0][4 * i + mm], w[0][4 * i + mm]);
                        float2 wz = make_float2(w[1][4 * i + mm], w[1][4 * i + mm]);
                        float2 wn = make_float2(w[2][4 * i + mm], w[2][4 * i + mm]);
#pragma unroll
                        for (int q = 0; q < 4; q++) {
                            float4 h4 = *(const float4*)(hr + 4 * q);
                            float2 h01 = make_float2(h4.x, h4.y);
                            float2 h23 = make_float2(h4.z, h4.w);
                            acc[2 * q][0]     = ffma2(h01, wr, acc[2 * q][0]);
                            acc[2 * q][1]     = ffma2(h01, wz, acc[2 * q][1]);
                            acc[2 * q][2]     = ffma2(h01, wn, acc[2 * q][2]);
                            acc[2 * q + 1][0] = ffma2(h23, wr, acc[2 * q + 1][0]);
                            acc[2 * q + 1][1] = ffma2(h23, wz, acc[2 * q + 1][1]);
                            acc[2 * q + 1][2] = ffma2(h23, wn, acc[2 * q + 1][2]);
                        }
                    }
                }
            }
        }

        // ---- vectorized dump: row = tid (stride RSTR), col = 4*b + g -------
        if (tid < 256) {
            float* rp = sred + tid * RSTR;
#pragma unroll
            for (int p = 0; p < 8; p++) {
                *(float4*)(rp + 8 * p)     = make_float4(acc[p][0].x, acc[p][1].x, acc[p][2].x, 0.f);
                *(float4*)(rp + 8 * p + 4) = make_float4(acc[p][0].y, acc[p][1].y, acc[p][2].y, 0.f);
            }
        }
        __syncthreads();

        // ---- vectorized reduce + gates + state update ----------------------
        float hn = 0.f;
        if (tid < 256) {
            float ghr = bh_r, ghz = bh_z, ghn = bh_n;
#pragma unroll
            for (int kc = 0; kc < 16; kc++) {
                float4 v = *(const float4*)(sred + (kc * 16 + jj) * RSTR + 4 * bbat);
                ghr += v.x; ghz += v.y; ghn += v.z;
            }
            float r = 1.f / (1.f + __expf(-(gir + ghr)));
            float z = 1.f / (1.f + __expf(-(giz + ghz)));
            float n = tanhf(gin + r * ghn);
            float hp = sh_h[(j0 + jj) * 16 + bbat];
            hn = (1.f - z) * n + z * hp;

            // exchange write for step s+1 (fresh addresses every step)
            g_hsT[((size_t)(s + 1) * 4 + grp) * (HID * 16) + (j0 + jj) * 16 + bbat] = hn;
        }
        __syncthreads();   // slice fully written before release

        if (tid == 0) {
            unsigned* ctr = &g_blk[(grp * 8 + own_blk) * 64];
            asm volatile("red.release.gpu.global.add.u32 [%0], 1;" :: "l"(ctr) : "memory");
        }
        // GEMM2-layout store (off critical path)
        if (tid < 256)
            g_hs[((size_t)s * BATCH + b0 + bbat) * HID + j0 + jj] = hn;
    }
}

// =============================================================================
extern "C" void kernel_launch(void* const* d_in, const int* in_sizes, int n_in,
                              void* d_out, int out_size)
{
    (void)in_sizes; (void)n_in; (void)out_size;
    const float* x     = (const float*)d_in[0];
    const float* w_ih  = (const float*)d_in[1];
    const float* w_hh  = (const float*)d_in[2];
    const float* b_ih  = (const float*)d_in[3];
    const float* b_hh  = (const float*)d_in[4];
    const float* w_out = (const float*)d_in[5];
    const float* b_out = (const float*)d_in[6];
    float* out = (float*)d_out;

    void *p_gi = nullptr, *p_hs = nullptr, *p_blk = nullptr;
    cudaGetSymbolAddress(&p_gi, g_gi);
    cudaGetSymbolAddress(&p_hs, g_hs);
    cudaGetSymbolAddress(&p_blk, g_blk);

    // reset block counters (captured into the graph, runs every replay)
    cudaMemsetAsync(p_blk, 0, sizeof(unsigned) * 4 * 8 * 64);

    const int scan_smem = (512 * 16 + 256 * RSTR) * 4;   // 100864 B
    cudaFuncSetAttribute(gru_scan, cudaFuncAttributeMaxDynamicSharedMemorySize, scan_smem);

    // Phase 1: gi = x @ w_ih^T + b_ih   (M=32768, N=1536, K=256)
    gemm_tn<IDIM, 0><<<dim3(GH / 128, (BATCH * S_LEN) / 128), 256>>>(
        x, w_ih, b_ih, (float*)p_gi);

    // Phase 2: 512-step GRU scan (persistent, 128 CTAs, dataflow exchange)
    gru_scan<<<128, 288, scan_smem>>>(w_hh, b_hh);

    // Phase 3: out = hs @ w_out^T + b_out   (M=32768, N=512, K=512)
    gemm_tn<HID, 1><<<dim3(ODIM / 128, (BATCH * S_LEN) / 128), 256>>>(
        (const float*)p_hs, w_out, b_out, out);
}

// round 5
// speedup vs baseline: 1.4779x; 1.4779x over previous
#include <cuda_runtime.h>
#include <cstring>

#define S_LEN 512
#define BATCH 64
#define IDIM  256
#define HID   512
#define GH    1536   // 3*HID
#define ODIM  512    // 2*O

#define RSTR 68      // sred row stride in floats: 272B = 16B-aligned, conflict-free

// ---------------- scratch (static device globals; no allocation) -------------
__device__ float    g_gi[(size_t)BATCH * S_LEN * GH];          // [B*S][3H] (row = b*512+s)
__device__ float    g_hs[(size_t)S_LEN * BATCH * HID];         // [S][B][H] -> GEMM2
__device__ float    g_hsT[(size_t)(S_LEN + 1) * 4 * HID * 16]; // [step][grp][k][b16]
__device__ unsigned g_blk[4 * 8 * 64];                          // per-(grp,block) counters, 256B apart

// ---------------- packed f32x2 FMA (full-rate fp32 on sm_100a) ---------------
__device__ __forceinline__ float2 ffma2(float2 a, float2 b, float2 c) {
#if defined(__CUDA_ARCH__) && (__CUDA_ARCH__ >= 1000)
    unsigned long long au, bu, cu, du;
    memcpy(&au, &a, 8); memcpy(&bu, &b, 8); memcpy(&cu, &c, 8);
    asm("fma.rn.f32x2 %0, %1, %2, %3;" : "=l"(du) : "l"(au), "l"(bu), "l"(cu));
    float2 d; memcpy(&d, &du, 8);
    return d;
#else
    return make_float2(fmaf(a.x, b.x, c.x), fmaf(a.y, b.y, c.y));
#endif
}

__device__ __forceinline__ void poll_ge(const unsigned* a, unsigned need) {
    unsigned v;
    do {
        asm volatile("ld.acquire.gpu.global.u32 %0, [%1];" : "=r"(v) : "l"(a) : "memory");
    } while (v < need);
}

// =============================================================================
// Tiled GEMM: C[M][N] = A[M][K] * B[N][K]^T + bias[N]
// 128x128 CTA tile, BLK_K=16, 256 threads, 8x8 per-thread tile (4+4 split),
// f32x2 FMAs, 2 CTAs/SM.  (unchanged from R4 — measured fma=65.6%)
// =============================================================================
template<int KDIM, int MODE>
__global__ __launch_bounds__(256, 2)
void gemm_tn(const float* __restrict__ A, const float* __restrict__ B,
             const float* __restrict__ bias, float* __restrict__ C)
{
    __shared__ float As[16 * 132];
    __shared__ float Bs[16 * 132];

    const int tid = threadIdx.x;
    const int m0 = blockIdx.y * 128;
    const int n0 = blockIdx.x * 128;
    const int lr = tid >> 2;
    const int lc = tid & 3;
    const int tx = tid & 15;
    const int ty = tid >> 4;

    const float* Ap = A + (size_t)(m0 + lr) * KDIM + lc * 4;
    const float* Bp = B + (size_t)(n0 + lr) * KDIM + lc * 4;

    float2 c2[8][4];
#pragma unroll
    for (int i = 0; i < 8; i++)
#pragma unroll
        for (int j = 0; j < 4; j++) c2[i][j] = make_float2(0.f, 0.f);

    float4 pa0 = *(const float4*)(Ap);
    float4 pa1 = *(const float4*)(Ap + (size_t)64 * KDIM);
    float4 pb0 = *(const float4*)(Bp);
    float4 pb1 = *(const float4*)(Bp + (size_t)64 * KDIM);

    const int KT = KDIM / 16;
    for (int kt = 0; kt < KT; kt++) {
        {
            const float* a0 = (const float*)&pa0;
            const float* a1 = (const float*)&pa1;
            const float* b0 = (const float*)&pb0;
            const float* b1 = (const float*)&pb1;
#pragma unroll
            for (int j = 0; j < 4; j++) {
                As[(lc * 4 + j) * 132 + lr]      = a0[j];
                As[(lc * 4 + j) * 132 + lr + 64] = a1[j];
                Bs[(lc * 4 + j) * 132 + lr]      = b0[j];
                Bs[(lc * 4 + j) * 132 + lr + 64] = b1[j];
            }
        }
        __syncthreads();
        if (kt + 1 < KT) {
            Ap += 16; Bp += 16;
            pa0 = *(const float4*)(Ap);
            pa1 = *(const float4*)(Ap + (size_t)64 * KDIM);
            pb0 = *(const float4*)(Bp);
            pb1 = *(const float4*)(Bp + (size_t)64 * KDIM);
        }
#pragma unroll
        for (int k = 0; k < 16; k++) {
            float4 a0 = *(const float4*)&As[k * 132 + ty * 4];
            float4 a1 = *(const float4*)&As[k * 132 + 64 + ty * 4];
            float4 b0 = *(const float4*)&Bs[k * 132 + tx * 4];
            float4 b1 = *(const float4*)&Bs[k * 132 + 64 + tx * 4];
            float av[8] = {a0.x, a0.y, a0.z, a0.w, a1.x, a1.y, a1.z, a1.w};
            float2 bv[4] = {{b0.x, b0.y}, {b0.z, b0.w}, {b1.x, b1.y}, {b1.z, b1.w}};
#pragma unroll
            for (int i = 0; i < 8; i++) {
                float2 ad = make_float2(av[i], av[i]);
#pragma unroll
                for (int j = 0; j < 4; j++) c2[i][j] = ffma2(ad, bv[j], c2[i][j]);
            }
        }
        __syncthreads();
    }

    int ncol[4];
    float2 bb[4];
#pragma unroll
    for (int j = 0; j < 4; j++) {
        ncol[j] = n0 + ((j < 2) ? (tx * 4 + 2 * j) : (64 + tx * 4 + 2 * (j - 2)));
        bb[j] = make_float2(bias[ncol[j]], bias[ncol[j] + 1]);
    }

#pragma unroll
    for (int i = 0; i < 8; i++) {
        int r = m0 + ((i < 4) ? (ty * 4 + i) : (64 + ty * 4 + (i - 4)));
        size_t rbase;
        if (MODE == 0) {
            rbase = (size_t)r * GH;
        } else {
            int s = r >> 6, b = r & 63;
            rbase = ((size_t)(b * S_LEN + s)) * ODIM;
        }
#pragma unroll
        for (int j = 0; j < 4; j++) {
            float2 v = make_float2(c2[i][j].x + bb[j].x, c2[i][j].y + bb[j].y);
            *(float2*)&C[rbase + ncol[j]] = v;
        }
    }
}

// =============================================================================
// GRU scan: 4 groups x 32 CTAs; slice = 16 j, weights register-resident.
// 256 threads = 8 warps. Monolithic step with WARP-PARALLEL exchange:
// warp w polls the per-(grp,block-w) counter (lane 0, acquire) and loads
// block w (64 k x 16 b = 4KB) into sh_h; all 8 warps in parallel; ONE
// __syncthreads; then the full 512-k FMA loop. Vectorized dump/reduce.
// =============================================================================
__global__ __launch_bounds__(256, 1)
void gru_scan(const float* __restrict__ w_hh, const float* __restrict__ b_hh)
{
    extern __shared__ float sm[];
    float* sh_h = sm;                 // 512*16 floats: h_s [k][b16]
    float* sred = sm + 512 * 16;      // 256 rows x RSTR floats

    const int tid     = threadIdx.x;
    const int lane    = tid & 31;
    const int wrp     = tid >> 5;     // warp id = exchange block id
    const int grp     = blockIdx.x >> 5;
    const int slice   = blockIdx.x & 31;
    const int j0      = slice * 16;
    const int b0      = grp * 16;
    const int own_blk = slice >> 2;   // block this CTA produces into
    const int kI      = tid >> 4;     // k interleave 0..15
    const int jI      = tid & 15;     // hidden unit in slice
    const int jj      = kI;           // gate-stage hidden idx
    const int bbat    = jI;           // gate-stage batch idx

    // ---- register-resident weights (natural k order: k = kI + 16*m) --------
    float w[3][32];
#pragma unroll
    for (int g = 0; g < 3; g++) {
        const float* p = w_hh + (size_t)(g * HID + j0 + jI) * HID + kI;
#pragma unroll
        for (int m = 0; m < 32; m++) w[g][m] = p[16 * m];
    }
    const float bh_r = b_hh[j0 + jj];
    const float bh_z = b_hh[HID + j0 + jj];
    const float bh_n = b_hh[2 * HID + j0 + jj];

    for (int i = tid; i < 512 * 16; i += 256) sh_h[i] = 0.f;   // h_0 = 0
    __syncthreads();

    for (int s = 0; s < S_LEN; s++) {
        // gi prefetch (consumed at gate stage; overlaps exchange+FMA)
        const float* gip = g_gi + ((size_t)((b0 + bbat) * S_LEN + s)) * GH + j0 + jj;
        float gir = gip[0], giz = gip[HID], gin = gip[2 * HID];

        float2 acc[8][3];
#pragma unroll
        for (int p = 0; p < 8; p++)
#pragma unroll
            for (int g = 0; g < 3; g++) acc[p][g] = make_float2(0.f, 0.f);

        if (s > 0) {
            // ---- warp-parallel exchange: warp w fetches block w ------------
            if (lane == 0) poll_ge(&g_blk[(grp * 8 + wrp) * 64], 4u * (unsigned)s);
            __syncwarp();
            const float4* src = (const float4*)(g_hsT + ((size_t)s * 4 + grp) * (HID * 16))
                                + wrp * 256 + lane;
            float4* dst = (float4*)sh_h + wrp * 256 + lane;
            float4 v0 = src[0],   v1 = src[32],  v2 = src[64],  v3 = src[96];
            float4 v4 = src[128], v5 = src[160], v6 = src[192], v7 = src[224];
            dst[0]   = v0; dst[32]  = v1; dst[64]  = v2; dst[96]  = v3;
            dst[128] = v4; dst[160] = v5; dst[192] = v6; dst[224] = v7;
            __syncthreads();

            // ---- full 512-k dot products (broadcast LDS, f32x2 FMA) --------
#pragma unroll
            for (int m = 0; m < 32; m++) {
                const float* hr = sh_h + (kI + 16 * m) * 16;
                float2 wr = make_float2(w[0][m], w[0][m]);
                float2 wz = make_float2(w[1][m], w[1][m]);
                float2 wn = make_float2(w[2][m], w[2][m]);
#pragma unroll
                for (int q = 0; q < 4; q++) {
                    float4 h4 = *(const float4*)(hr + 4 * q);
                    float2 h01 = make_float2(h4.x, h4.y);
                    float2 h23 = make_float2(h4.z, h4.w);
                    acc[2 * q][0]     = ffma2(h01, wr, acc[2 * q][0]);
                    acc[2 * q][1]     = ffma2(h01, wz, acc[2 * q][1]);
                    acc[2 * q][2]     = ffma2(h01, wn, acc[2 * q][2]);
                    acc[2 * q + 1][0] = ffma2(h23, wr, acc[2 * q + 1][0]);
                    acc[2 * q + 1][1] = ffma2(h23, wz, acc[2 * q + 1][1]);
                    acc[2 * q + 1][2] = ffma2(h23, wn, acc[2 * q + 1][2]);
                }
            }
        }

        // ---- vectorized dump: row = tid (stride RSTR), col = 4*b + g -------
        {
            float* rp = sred + tid * RSTR;
#pragma unroll
            for (int p = 0; p < 8; p++) {
                *(float4*)(rp + 8 * p)     = make_float4(acc[p][0].x, acc[p][1].x, acc[p][2].x, 0.f);
                *(float4*)(rp + 8 * p + 4) = make_float4(acc[p][0].y, acc[p][1].y, acc[p][2].y, 0.f);
            }
        }
        __syncthreads();

        // ---- vectorized reduce + gates + state update ----------------------
        float ghr = bh_r, ghz = bh_z, ghn = bh_n;
#pragma unroll
        for (int kc = 0; kc < 16; kc++) {
            float4 v = *(const float4*)(sred + (kc * 16 + jj) * RSTR + 4 * bbat);
            ghr += v.x; ghz += v.y; ghn += v.z;
        }
        float r = 1.f / (1.f + __expf(-(gir + ghr)));
        float z = 1.f / (1.f + __expf(-(giz + ghz)));
        float n = tanhf(gin + r * ghn);
        float hp = sh_h[(j0 + jj) * 16 + bbat];
        float hn = (1.f - z) * n + z * hp;

        // exchange write for step s+1 (fresh addresses every step)
        g_hsT[((size_t)(s + 1) * 4 + grp) * (HID * 16) + (j0 + jj) * 16 + bbat] = hn;
        __syncthreads();   // slice fully written before release

        if (tid == 0) {
            unsigned* ctr = &g_blk[(grp * 8 + own_blk) * 64];
            asm volatile("red.release.gpu.global.add.u32 [%0], 1;" :: "l"(ctr) : "memory");
        }
        // GEMM2-layout store (off critical path; overlaps next poll)
        g_hs[((size_t)s * BATCH + b0 + bbat) * HID + j0 + jj] = hn;
    }
}

// =============================================================================
extern "C" void kernel_launch(void* const* d_in, const int* in_sizes, int n_in,
                              void* d_out, int out_size)
{
    (void)in_sizes; (void)n_in; (void)out_size;
    const float* x     = (const float*)d_in[0];
    const float* w_ih  = (const float*)d_in[1];
    const float* w_hh  = (const float*)d_in[2];
    const float* b_ih  = (const float*)d_in[3];
    const float* b_hh  = (const float*)d_in[4];
    const float* w_out = (const float*)d_in[5];
    const float* b_out = (const float*)d_in[6];
    float* out = (float*)d_out;

    void *p_gi = nullptr, *p_hs = nullptr, *p_blk = nullptr;
    cudaGetSymbolAddress(&p_gi, g_gi);
    cudaGetSymbolAddress(&p_hs, g_hs);
    cudaGetSymbolAddress(&p_blk, g_blk);

    // reset block counters (captured into the graph, runs every replay)
    cudaMemsetAsync(p_blk, 0, sizeof(unsigned) * 4 * 8 * 64);

    const int scan_smem = (512 * 16 + 256 * RSTR) * 4;   // 102400 B
    cudaFuncSetAttribute(gru_scan, cudaFuncAttributeMaxDynamicSharedMemorySize, scan_smem);

    // Phase 1: gi = x @ w_ih^T + b_ih   (M=32768, N=1536, K=256)
    gemm_tn<IDIM, 0><<<dim3(GH / 128, (BATCH * S_LEN) / 128), 256>>>(
        x, w_ih, b_ih, (float*)p_gi);

    // Phase 2: 512-step GRU scan (persistent, 128 CTAs, warp-parallel exchange)
    gru_scan<<<128, 256, scan_smem>>>(w_hh, b_hh);

    // Phase 3: out = hs @ w_out^T + b_out   (M=32768, N=512, K=512)
    gemm_tn<HID, 1><<<dim3(ODIM / 128, (BATCH * S_LEN) / 128), 256>>>(
        (const float*)p_hs, w_out, b_out, out);
}

// round 6
// speedup vs baseline: 1.6296x; 1.1026x over previous
#include <cuda_runtime.h>
#include <cstring>

#define S_LEN 512
#define BATCH 64
#define IDIM  256
#define HID   512
#define GH    1536   // 3*HID
#define ODIM  512    // 2*O

#define RSTR 68      // sred row stride in floats: 272B = 16B-aligned, conflict-free

// ---------------- scratch (static device globals; no allocation) -------------
__device__ float    g_hs [(size_t)S_LEN * BATCH * HID];         // [S][B][H] -> GEMM2
__device__ float    g_hsT[(size_t)(S_LEN + 1) * 4 * HID * 16];  // [step][grp][k][b16]
__device__ float    g_xT [(size_t)S_LEN * 4 * IDIM * 16];       // [s][grp][k][b16]
__device__ unsigned g_blk[4 * 8 * 64];                          // per-(grp,block) counters

// ---------------- packed f32x2 FMA (full-rate fp32 on sm_100a) ---------------
__device__ __forceinline__ float2 ffma2(float2 a, float2 b, float2 c) {
#if defined(__CUDA_ARCH__) && (__CUDA_ARCH__ >= 1000)
    unsigned long long au, bu, cu, du;
    memcpy(&au, &a, 8); memcpy(&bu, &b, 8); memcpy(&cu, &c, 8);
    asm("fma.rn.f32x2 %0, %1, %2, %3;" : "=l"(du) : "l"(au), "l"(bu), "l"(cu));
    float2 d; memcpy(&d, &du, 8);
    return d;
#else
    return make_float2(fmaf(a.x, b.x, c.x), fmaf(a.y, b.y, c.y));
#endif
}

__device__ __forceinline__ void poll_ge(const unsigned* a, unsigned need) {
    unsigned v;
    do {
        asm volatile("ld.acquire.gpu.global.u32 %0, [%1];" : "=r"(v) : "l"(a) : "memory");
    } while (v < need);
}

__device__ __forceinline__ float fast_sigmoid(float x) {
    return __fdividef(1.f, 1.f + __expf(-x));
}
__device__ __forceinline__ float fast_tanh(float x) {
    return __fdividef(2.f, 1.f + __expf(-2.f * x)) - 1.f;
}

// =============================================================================
// Prologue: x[b][s][k] -> g_xT[s][grp][k][b16]  (smem transpose, coalesced)
// =============================================================================
__global__ __launch_bounds__(256)
void transpose_x(const float* __restrict__ x)
{
    __shared__ float ts[16 * 260];
    const int tid = threadIdx.x;
    const int sg  = blockIdx.x;          // s*4 + grp
    const int s   = sg >> 2, grp = sg & 3;
    const int bb  = tid >> 4, kq = tid & 15;

    const float* src = x + ((size_t)(grp * 16 + bb) * S_LEN + s) * IDIM + kq * 16;
#pragma unroll
    for (int i = 0; i < 4; i++)
        *(float4*)(ts + bb * 260 + kq * 16 + 4 * i) = *(const float4*)(src + 4 * i);
    __syncthreads();

    float* dst = g_xT + ((size_t)sg * 256 + tid) * 16;
#pragma unroll
    for (int q = 0; q < 4; q++) {
        float4 o;
        o.x = ts[(4 * q + 0) * 260 + tid];
        o.y = ts[(4 * q + 1) * 260 + tid];
        o.z = ts[(4 * q + 2) * 260 + tid];
        o.w = ts[(4 * q + 3) * 260 + tid];
        *(float4*)(dst + 4 * q) = o;
    }
}

// =============================================================================
// Tiled GEMM (output projection only): C[M][N] = A[M][K]*B[N][K]^T + bias[N]
// =============================================================================
template<int KDIM, int MODE>
__global__ __launch_bounds__(256, 2)
void gemm_tn(const float* __restrict__ A, const float* __restrict__ B,
             const float* __restrict__ bias, float* __restrict__ C)
{
    __shared__ float As[16 * 132];
    __shared__ float Bs[16 * 132];

    const int tid = threadIdx.x;
    const int m0 = blockIdx.y * 128;
    const int n0 = blockIdx.x * 128;
    const int lr = tid >> 2;
    const int lc = tid & 3;
    const int tx = tid & 15;
    const int ty = tid >> 4;

    const float* Ap = A + (size_t)(m0 + lr) * KDIM + lc * 4;
    const float* Bp = B + (size_t)(n0 + lr) * KDIM + lc * 4;

    float2 c2[8][4];
#pragma unroll
    for (int i = 0; i < 8; i++)
#pragma unroll
        for (int j = 0; j < 4; j++) c2[i][j] = make_float2(0.f, 0.f);

    float4 pa0 = *(const float4*)(Ap);
    float4 pa1 = *(const float4*)(Ap + (size_t)64 * KDIM);
    float4 pb0 = *(const float4*)(Bp);
    float4 pb1 = *(const float4*)(Bp + (size_t)64 * KDIM);

    const int KT = KDIM / 16;
    for (int kt = 0; kt < KT; kt++) {
        {
            const float* a0 = (const float*)&pa0;
            const float* a1 = (const float*)&pa1;
            const float* b0 = (const float*)&pb0;
            const float* b1 = (const float*)&pb1;
#pragma unroll
            for (int j = 0; j < 4; j++) {
                As[(lc * 4 + j) * 132 + lr]      = a0[j];
                As[(lc * 4 + j) * 132 + lr + 64] = a1[j];
                Bs[(lc * 4 + j) * 132 + lr]      = b0[j];
                Bs[(lc * 4 + j) * 132 + lr + 64] = b1[j];
            }
        }
        __syncthreads();
        if (kt + 1 < KT) {
            Ap += 16; Bp += 16;
            pa0 = *(const float4*)(Ap);
            pa1 = *(const float4*)(Ap + (size_t)64 * KDIM);
            pb0 = *(const float4*)(Bp);
            pb1 = *(const float4*)(Bp + (size_t)64 * KDIM);
        }
#pragma unroll
        for (int k = 0; k < 16; k++) {
            float4 a0 = *(const float4*)&As[k * 132 + ty * 4];
            float4 a1 = *(const float4*)&As[k * 132 + 64 + ty * 4];
            float4 b0 = *(const float4*)&Bs[k * 132 + tx * 4];
            float4 b1 = *(const float4*)&Bs[k * 132 + 64 + tx * 4];
            float av[8] = {a0.x, a0.y, a0.z, a0.w, a1.x, a1.y, a1.z, a1.w};
            float2 bv[4] = {{b0.x, b0.y}, {b0.z, b0.w}, {b1.x, b1.y}, {b1.z, b1.w}};
#pragma unroll
            for (int i = 0; i < 8; i++) {
                float2 ad = make_float2(av[i], av[i]);
#pragma unroll
                for (int j = 0; j < 4; j++) c2[i][j] = ffma2(ad, bv[j], c2[i][j]);
            }
        }
        __syncthreads();
    }

    int ncol[4];
    float2 bb[4];
#pragma unroll
    for (int j = 0; j < 4; j++) {
        ncol[j] = n0 + ((j < 2) ? (tx * 4 + 2 * j) : (64 + tx * 4 + 2 * (j - 2)));
        bb[j] = make_float2(bias[ncol[j]], bias[ncol[j] + 1]);
    }

#pragma unroll
    for (int i = 0; i < 8; i++) {
        int r = m0 + ((i < 4) ? (ty * 4 + i) : (64 + ty * 4 + (i - 4)));
        size_t rbase;
        if (MODE == 0) {
            rbase = (size_t)r * GH;
        } else {
            int s = r >> 6, b = r & 63;
            rbase = ((size_t)(b * S_LEN + s)) * ODIM;
        }
#pragma unroll
        for (int j = 0; j < 4; j++) {
            float2 v = make_float2(c2[i][j].x + bb[j].x, c2[i][j].y + bb[j].y);
            *(float2*)&C[rbase + ncol[j]] = v;
        }
    }
}

// =============================================================================
// Fused GRU scan (computes gi in-step; GEMM1 eliminated).
// 4 groups x 32 CTAs; slice = 16 j. w_hh register-resident; w_ih SMEM-resident
// (pad 257 -> conflict-free). Per step:
//   gi chunk A (x static, no sync needed) | poll+LDG h | gi chunk B (hides LDG)
//   STS h; bar; gh-FMA; dump 4-plane partials (16 waste-free STS.128); bar;
//   x(s+1) prefetch LDG; reduce (16 LDS.128) + gates; stores; bar; release.
// Acc planes: 0 = gi_r+gh_r, 1 = gi_z+gh_z, 2 = gh_n, 3 = gi_n.
// =============================================================================
__global__ __launch_bounds__(256, 1)
void gru_scan(const float* __restrict__ w_ih, const float* __restrict__ w_hh,
              const float* __restrict__ b_ih, const float* __restrict__ b_hh)
{
    extern __shared__ float sm[];
    float* sh_h = sm;                      // 8192  : h [k512][b16]
    float* sred = sm + 8192;               // 17408 : partials 256 x RSTR
    float* sx   = sm + 8192 + 17408;       // 8192  : x tiles, 2 x [k256][b16]
    float* sw   = sx + 8192;               // 12336 : w_ih slice [48][257]

    const int tid     = threadIdx.x;
    const int lane    = tid & 31;
    const int wrp     = tid >> 5;          // warp id = exchange block id
    const int grp     = blockIdx.x >> 5;
    const int slice   = blockIdx.x & 31;
    const int j0      = slice * 16;
    const int b0      = grp * 16;
    const int own_blk = slice >> 2;
    const int kI      = tid >> 4;          // k-chunk id 0..15
    const int jI      = tid & 15;          // hidden unit in slice
    const int jj      = kI;                // gate-stage hidden idx
    const int bbat    = jI;                // gate-stage batch idx

    // ---- w_hh register-resident (k = kI + 16*m) ----------------------------
    float w[3][32];
#pragma unroll
    for (int g = 0; g < 3; g++) {
        const float* p = w_hh + (size_t)(g * HID + j0 + jI) * HID + kI;
#pragma unroll
        for (int m = 0; m < 32; m++) w[g][m] = p[16 * m];
    }

    // ---- stage w_ih slice into SMEM (rows (g,j), pad 257) ------------------
    for (int i = tid; i < 48 * 256; i += 256) {
        int row = i >> 8, k = i & 255;
        int g = row >> 4, jr = row & 15;
        sw[row * 257 + k] = w_ih[(size_t)(g * HID + j0 + jr) * IDIM + k];
    }

    // ---- fused biases ------------------------------------------------------
    const float bR  = b_ih[j0 + jj]           + b_hh[j0 + jj];
    const float bZ  = b_ih[HID + j0 + jj]     + b_hh[HID + j0 + jj];
    const float bIN = b_ih[2 * HID + j0 + jj];
    const float bHN = b_hh[2 * HID + j0 + jj];

    for (int i = tid; i < 8192; i += 256) sh_h[i] = 0.f;   // h_0 = 0
    {   // stage x tile for step 0
        const float4* src = (const float4*)(g_xT + (size_t)grp * 4096);
        float4* dst = (float4*)sx;
#pragma unroll
        for (int i = 0; i < 4; i++) dst[tid + 256 * i] = src[tid + 256 * i];
    }
    __syncthreads();

    for (int s = 0; s < S_LEN; s++) {
        float2 acc[8][4];
#pragma unroll
        for (int p = 0; p < 8; p++)
#pragma unroll
            for (int g = 0; g < 4; g++) acc[p][g] = make_float2(0.f, 0.f);

        const float* xrow = sx + (s & 1) * 4096 + kI * 256;   // x rows for this k-chunk
        const float* swr = sw + jI * 257        + kI * 16;
        const float* swz = sw + (16 + jI) * 257 + kI * 16;
        const float* swn = sw + (32 + jI) * 257 + kI * 16;

        // ---- gi chunk A (kk 0..7) -----------------------------------------
#pragma unroll 4
        for (int kk = 0; kk < 8; kk++) {
            float wr = swr[kk], wz = swz[kk], wn = swn[kk];
            float2 WR = {wr, wr}, WZ = {wz, wz}, WN = {wn, wn};
            const float* xr = xrow + kk * 16;
#pragma unroll
            for (int q = 0; q < 4; q++) {
                float4 x4 = *(const float4*)(xr + 4 * q);
                float2 x01 = {x4.x, x4.y}, x23 = {x4.z, x4.w};
                acc[2 * q][0]     = ffma2(x01, WR, acc[2 * q][0]);
                acc[2 * q][1]     = ffma2(x01, WZ, acc[2 * q][1]);
                acc[2 * q][3]     = ffma2(x01, WN, acc[2 * q][3]);
                acc[2 * q + 1][0] = ffma2(x23, WR, acc[2 * q + 1][0]);
                acc[2 * q + 1][1] = ffma2(x23, WZ, acc[2 * q + 1][1]);
                acc[2 * q + 1][3] = ffma2(x23, WN, acc[2 * q + 1][3]);
            }
        }

        // ---- poll (fast path: producers released during gi A) + LDG h -----
        float4 h0, h1, h2, h3, h4, h5, h6, h7;
        if (s > 0) {
            if (lane == 0) poll_ge(&g_blk[(grp * 8 + wrp) * 64], 4u * (unsigned)s);
            __syncwarp();
            const float4* srcb = (const float4*)(g_hsT + ((size_t)s * 4 + grp) * 8192)
                                 + wrp * 256 + lane;
            h0 = srcb[0];   h1 = srcb[32];  h2 = srcb[64];  h3 = srcb[96];
            h4 = srcb[128]; h5 = srcb[160]; h6 = srcb[192]; h7 = srcb[224];
        }

        // ---- gi chunk B (kk 8..15) — hides h LDG latency -------------------
#pragma unroll 4
        for (int kk = 8; kk < 16; kk++) {
            float wr = swr[kk], wz = swz[kk], wn = swn[kk];
            float2 WR = {wr, wr}, WZ = {wz, wz}, WN = {wn, wn};
            const float* xr = xrow + kk * 16;
#pragma unroll
            for (int q = 0; q < 4; q++) {
                float4 x4 = *(const float4*)(xr + 4 * q);
                float2 x01 = {x4.x, x4.y}, x23 = {x4.z, x4.w};
                acc[2 * q][0]     = ffma2(x01, WR, acc[2 * q][0]);
                acc[2 * q][1]     = ffma2(x01, WZ, acc[2 * q][1]);
                acc[2 * q][3]     = ffma2(x01, WN, acc[2 * q][3]);
                acc[2 * q + 1][0] = ffma2(x23, WR, acc[2 * q + 1][0]);
                acc[2 * q + 1][1] = ffma2(x23, WZ, acc[2 * q + 1][1]);
                acc[2 * q + 1][3] = ffma2(x23, WN, acc[2 * q + 1][3]);
            }
        }

        if (s > 0) {
            float4* dstb = (float4*)sh_h + wrp * 256 + lane;
            dstb[0]   = h0; dstb[32]  = h1; dstb[64]  = h2; dstb[96]  = h3;
            dstb[128] = h4; dstb[160] = h5; dstb[192] = h6; dstb[224] = h7;
        }
        __syncthreads();

        // ---- gh-FMA over full 512 k (planes 0,1,2) -------------------------
        if (s > 0) {
#pragma unroll
            for (int m = 0; m < 32; m++) {
                const float* hr = sh_h + (kI + 16 * m) * 16;
                float2 WR = {w[0][m], w[0][m]};
                float2 WZ = {w[1][m], w[1][m]};
                float2 WN = {w[2][m], w[2][m]};
#pragma unroll
                for (int q = 0; q < 4; q++) {
                    float4 h4v = *(const float4*)(hr + 4 * q);
                    float2 h01 = {h4v.x, h4v.y}, h23 = {h4v.z, h4v.w};
                    acc[2 * q][0]     = ffma2(h01, WR, acc[2 * q][0]);
                    acc[2 * q][1]     = ffma2(h01, WZ, acc[2 * q][1]);
                    acc[2 * q][2]     = ffma2(h01, WN, acc[2 * q][2]);
                    acc[2 * q + 1][0] = ffma2(h23, WR, acc[2 * q + 1][0]);
                    acc[2 * q + 1][1] = ffma2(h23, WZ, acc[2 * q + 1][1]);
                    acc[2 * q + 1][2] = ffma2(h23, WN, acc[2 * q + 1][2]);
                }
            }
        }

        // ---- dump: 16 waste-free STS.128 (float4 = 4 planes per batch) -----
        {
            float* rp = sred + tid * RSTR;
#pragma unroll
            for (int p = 0; p < 8; p++) {
                *(float4*)(rp + 8 * p)     =
                    make_float4(acc[p][0].x, acc[p][1].x, acc[p][2].x, acc[p][3].x);
                *(float4*)(rp + 8 * p + 4) =
                    make_float4(acc[p][0].y, acc[p][1].y, acc[p][2].y, acc[p][3].y);
            }
        }
        __syncthreads();

        // ---- x prefetch for s+1 (coalesced, consumed after reduce) ---------
        float4 xf0, xf1, xf2, xf3;
        if (s + 1 < S_LEN) {
            const float4* xsrc = (const float4*)(g_xT + ((size_t)(s + 1) * 4 + grp) * 4096);
            xf0 = xsrc[tid]; xf1 = xsrc[tid + 256]; xf2 = xsrc[tid + 512]; xf3 = xsrc[tid + 768];
        }

        // ---- reduce + gates -------------------------------------------------
        float R = bR, Z = bZ, GN = 0.f, GI = bIN;
#pragma unroll
        for (int kc = 0; kc < 16; kc++) {
            float4 v = *(const float4*)(sred + (kc * 16 + jj) * RSTR + 4 * bbat);
            R += v.x; Z += v.y; GN += v.z; GI += v.w;
        }
        float r = fast_sigmoid(R);
        float z = fast_sigmoid(Z);
        float n = fast_tanh(GI + r * (GN + bHN));
        float hp = sh_h[(j0 + jj) * 16 + bbat];
        float hn = (1.f - z) * n + z * hp;

        g_hsT[((size_t)(s + 1) * 4 + grp) * 8192 + (j0 + jj) * 16 + bbat] = hn;
        g_hs[((size_t)s * BATCH + b0 + bbat) * HID + j0 + jj] = hn;

        if (s + 1 < S_LEN) {
            float4* xd = (float4*)(sx + ((s + 1) & 1) * 4096);
            xd[tid] = xf0; xd[tid + 256] = xf1; xd[tid + 512] = xf2; xd[tid + 768] = xf3;
        }
        __syncthreads();   // h + x tile visible before release / next gi

        if (tid == 0) {
            unsigned* ctr = &g_blk[(grp * 8 + own_blk) * 64];
            asm volatile("red.release.gpu.global.add.u32 [%0], 1;" :: "l"(ctr) : "memory");
        }
    }
}

// =============================================================================
extern "C" void kernel_launch(void* const* d_in, const int* in_sizes, int n_in,
                              void* d_out, int out_size)
{
    (void)in_sizes; (void)n_in; (void)out_size;
    const float* x     = (const float*)d_in[0];
    const float* w_ih  = (const float*)d_in[1];
    const float* w_hh  = (const float*)d_in[2];
    const float* b_ih  = (const float*)d_in[3];
    const float* b_hh  = (const float*)d_in[4];
    const float* w_out = (const float*)d_in[5];
    const float* b_out = (const float*)d_in[6];
    float* out = (float*)d_out;

    void *p_hs = nullptr, *p_blk = nullptr;
    cudaGetSymbolAddress(&p_hs, g_hs);
    cudaGetSymbolAddress(&p_blk, g_blk);

    cudaMemsetAsync(p_blk, 0, sizeof(unsigned) * 4 * 8 * 64);

    const int scan_smem = (8192 + 256 * RSTR + 8192 + 48 * 257) * 4;   // 184512 B
    cudaFuncSetAttribute(gru_scan, cudaFuncAttributeMaxDynamicSharedMemorySize, scan_smem);

    // Phase 0: transpose x into [s][grp][k][b16]
    transpose_x<<<S_LEN * 4, 256>>>(x);

    // Phase 1+2 fused: 512-step GRU scan with in-step gi computation
    gru_scan<<<128, 256, scan_smem>>>(w_ih, w_hh, b_ih, b_hh);

    // Phase 3: out = hs @ w_out^T + b_out   (M=32768, N=512, K=512)
    gemm_tn<HID, 1><<<dim3(ODIM / 128, (BATCH * S_LEN) / 128), 256>>>(
        (const float*)p_hs, w_out, b_out, out);
}